// round 1
// baseline (speedup 1.0000x reference)
#include <cuda_runtime.h>

#define FULLMASK 0xffffffffu
#define NB 1024
#define SQ 128
#define T8 8

// ---- constants matching the reference (C=1.2) ----
__device__ __forceinline__ float kSQC()  { return 1.0954451150103321f; }           // sqrt(1.2)
__device__ __forceinline__ float kMaxN() { return 0.90921944545857576f; }          // (1-4e-3)/sqrt(1.2)
#define K_C   1.2f
#define K_MIN 1e-15f

// scratch for inter-kernel token features (no cudaMalloc allowed)
__device__ float g_oe[NB * SQ * 128];
__device__ float g_oh[NB * SQ * 128];

__device__ __forceinline__ float wsum(float v) {
    v += __shfl_xor_sync(FULLMASK, v, 16);
    v += __shfl_xor_sync(FULLMASK, v, 8);
    v += __shfl_xor_sync(FULLMASK, v, 4);
    v += __shfl_xor_sync(FULLMASK, v, 2);
    v += __shfl_xor_sync(FULLMASK, v, 1);
    return v;
}

__device__ __forceinline__ float artanh_c(float z) {
    z = fminf(z, 1.0f - 1e-7f);
    return 0.5f * logf((1.0f + z) / (1.0f - z));
}

// ---- warp-tiled matvec: y[j] = sum_k W[j,k] x[k] for 8 tokens ----
// Wt is K x Jpad (transposed, zero-padded beyond J). j = lane + 32*r.
template<int K, int Jpad, int R>
__device__ __forceinline__ void matvec8(const float* __restrict__ Wt,
                                        const float (&xin)[(K + 31) / 32][T8],
                                        float (&acc)[R][T8]) {
    const int lane = threadIdx.x & 31;
#pragma unroll
    for (int r = 0; r < R; r++)
#pragma unroll
        for (int t = 0; t < T8; t++) acc[r][t] = 0.f;
    constexpr int KREG = (K + 31) / 32;
#pragma unroll
    for (int kr = 0; kr < KREG; kr++) {
        const int kmax = (K - kr * 32 < 32) ? (K - kr * 32) : 32;
        const float* Wrow = Wt + kr * 32 * Jpad + lane;
#pragma unroll 4
        for (int kl = 0; kl < kmax; kl++) {
            float xk[T8];
#pragma unroll
            for (int t = 0; t < T8; t++) xk[t] = __shfl_sync(FULLMASK, xin[kr][t], kl);
            const float* w = Wrow + kl * Jpad;
#pragma unroll
            for (int r = 0; r < R; r++) {
                float wv = w[32 * r];
#pragma unroll
                for (int t = 0; t < T8; t++) acc[r][t] = fmaf(wv, xk[t], acc[r][t]);
            }
        }
    }
}

template<int R>
__device__ __forceinline__ void sumsq8(const float (&v)[R][T8], float (&o)[T8]) {
    float p[T8];
#pragma unroll
    for (int t = 0; t < T8; t++) {
        p[t] = 0.f;
#pragma unroll
        for (int r = 0; r < R; r++) p[t] = fmaf(v[r][t], v[r][t], p[t]);
    }
#pragma unroll
    for (int t = 0; t < T8; t++) o[t] = wsum(p[t]);
}

template<int R>
__device__ __forceinline__ void projx8(float (&v)[R][T8]) {
    float s2[T8];
    sumsq8<R>(v, s2);
    float f[T8];
#pragma unroll
    for (int t = 0; t < T8; t++) {
        float n = fmaxf(sqrtf(s2[t]), K_MIN);
        f[t] = (n > kMaxN()) ? (kMaxN() / n) : 1.0f;
    }
#pragma unroll
    for (int r = 0; r < R; r++)
#pragma unroll
        for (int t = 0; t < T8; t++) v[r][t] *= f[t];
}

template<int R>
__device__ __forceinline__ void expmap0_8(float (&v)[R][T8]) {
    float s2[T8];
    sumsq8<R>(v, s2);
    float sc[T8];
#pragma unroll
    for (int t = 0; t < T8; t++) {
        float n = fmaxf(sqrtf(s2[t]), K_MIN);
        float tt = tanhf(fminf(kSQC() * n, 15.f));
        sc[t] = tt / (kSQC() * n);
    }
#pragma unroll
    for (int r = 0; r < R; r++)
#pragma unroll
        for (int t = 0; t < T8; t++) v[r][t] *= sc[t];
    projx8<R>(v);
}

template<int R>
__device__ __forceinline__ void logmap0_8(float (&v)[R][T8]) {
    float s2[T8];
    sumsq8<R>(v, s2);
    float sc[T8];
#pragma unroll
    for (int t = 0; t < T8; t++) {
        float n = fmaxf(sqrtf(s2[t]), K_MIN);
        sc[t] = artanh_c(kSQC() * n) / (kSQC() * n);
    }
#pragma unroll
    for (int r = 0; r < R; r++)
#pragma unroll
        for (int t = 0; t < T8; t++) v[r][t] *= sc[t];
}

template<int R>
__device__ __forceinline__ void mobrelu8(float (&v)[R][T8]) {
    logmap0_8<R>(v);
#pragma unroll
    for (int r = 0; r < R; r++)
#pragma unroll
        for (int t = 0; t < T8; t++) v[r][t] = fmaxf(v[r][t], 0.f);
    expmap0_8<R>(v);
}

template<int R>
__device__ __forceinline__ void addbias_relu8(const float* __restrict__ bs, float (&v)[R][T8]) {
    const int lane = threadIdx.x & 31;
#pragma unroll
    for (int r = 0; r < R; r++) {
        float b = bs[lane + 32 * r];
#pragma unroll
        for (int t = 0; t < T8; t++) v[r][t] = fmaxf(v[r][t] + b, 0.f);
    }
}

template<int R>
__device__ __forceinline__ void addbias8(const float* __restrict__ bs, float (&v)[R][T8]) {
    const int lane = threadIdx.x & 31;
#pragma unroll
    for (int r = 0; r < R; r++) {
        float b = bs[lane + 32 * r];
#pragma unroll
        for (int t = 0; t < T8; t++) v[r][t] = v[r][t] + b;
    }
}

// p_linear on PoincareBall: projx(mobius_add(projx(mobius_matvec), expmap0(b)))
// eb = expmap0(b) precomputed in smem (padded zeros), ebn2 = ||eb||^2
template<int K, int Jpad, int R>
__device__ __forceinline__ void hyp_linear8(const float* __restrict__ Wt,
                                            const float* __restrict__ eb, float ebn2,
                                            const float (&xin)[(K + 31) / 32][T8],
                                            float (&out)[R][T8]) {
    const int lane = threadIdx.x & 31;
    float xn2[T8];
    sumsq8<(K + 31) / 32>(xin, xn2);
    matvec8<K, Jpad, R>(Wt, xin, out);
    float mn2[T8];
    sumsq8<R>(out, mn2);
    float sc[T8];
#pragma unroll
    for (int t = 0; t < T8; t++) {
        float xn = fmaxf(sqrtf(xn2[t]), K_MIN);
        float mn = fmaxf(sqrtf(mn2[t]), K_MIN);
        float ar = artanh_c(kSQC() * xn);
        float tt = tanhf(fminf(mn / xn * ar, 15.f));
        sc[t] = (mn2[t] == 0.f) ? 0.f : tt / (mn * kSQC());
    }
#pragma unroll
    for (int r = 0; r < R; r++)
#pragma unroll
        for (int t = 0; t < T8; t++) out[r][t] *= sc[t];
    projx8<R>(out);
    // mobius_add(out, eb)
    float x2[T8];
    sumsq8<R>(out, x2);
    float xy[T8];
    {
        float p[T8];
#pragma unroll
        for (int t = 0; t < T8; t++) p[t] = 0.f;
#pragma unroll
        for (int r = 0; r < R; r++) {
            float e = eb[lane + 32 * r];
#pragma unroll
            for (int t = 0; t < T8; t++) p[t] = fmaf(out[r][t], e, p[t]);
        }
#pragma unroll
        for (int t = 0; t < T8; t++) xy[t] = wsum(p[t]);
    }
    float ca[T8], cb[T8], iv[T8];
#pragma unroll
    for (int t = 0; t < T8; t++) {
        ca[t] = 1.f + 2.f * K_C * xy[t] + K_C * ebn2;
        cb[t] = 1.f - K_C * x2[t];
        float dn = 1.f + 2.f * K_C * xy[t] + K_C * K_C * x2[t] * ebn2;
        iv[t] = 1.f / fmaxf(dn, K_MIN);
    }
#pragma unroll
    for (int r = 0; r < R; r++) {
        float e = eb[lane + 32 * r];
#pragma unroll
        for (int t = 0; t < T8; t++) out[r][t] = (ca[t] * out[r][t] + cb[t] * e) * iv[t];
    }
    projx8<R>(out);
}

// ---- cooperative smem loaders ----
__device__ __forceinline__ void loadWt(float* dst, const float* __restrict__ W,
                                       int J, int K, int Jpad) {
    int n = K * Jpad;
    for (int i = threadIdx.x; i < n; i += blockDim.x) {
        int k = i / Jpad;
        int j = i - k * Jpad;
        dst[i] = (j < J) ? W[j * K + k] : 0.f;
    }
}
__device__ __forceinline__ void loadVec(float* dst, const float* __restrict__ v, int J, int Jpad) {
    for (int i = threadIdx.x; i < Jpad; i += blockDim.x) dst[i] = (i < J) ? v[i] : 0.f;
}

// warp-level expmap0 of a bias vector in smem (padded), also stores ||eb||^2
template<int R>
__device__ __forceinline__ void expmap_smem(float* v, float* n2out) {
    const int lane = threadIdx.x & 31;
    float a[R];
    float p = 0.f;
#pragma unroll
    for (int r = 0; r < R; r++) {
        a[r] = v[lane + 32 * r];
        p = fmaf(a[r], a[r], p);
    }
    p = wsum(p);
    float n = fmaxf(sqrtf(p), K_MIN);
    float tt = tanhf(fminf(kSQC() * n, 15.f));
    float scv = tt / (kSQC() * n);
#pragma unroll
    for (int r = 0; r < R; r++) a[r] *= scv;
    float q = 0.f;
#pragma unroll
    for (int r = 0; r < R; r++) q = fmaf(a[r], a[r], q);
    q = wsum(q);
    float nn = fmaxf(sqrtf(q), K_MIN);
    if (nn > kMaxN()) {
        float f = kMaxN() / nn;
#pragma unroll
        for (int r = 0; r < R; r++) a[r] *= f;
    }
    float y2 = 0.f;
#pragma unroll
    for (int r = 0; r < R; r++) y2 = fmaf(a[r], a[r], y2);
    y2 = wsum(y2);
#pragma unroll
    for (int r = 0; r < R; r++) v[lane + 32 * r] = a[r];
    if (lane == 0) *n2out = y2;
}

extern __shared__ float sm[];

// ================= Kernel 1: both MLP branches per token =================
__global__ void __launch_bounds__(512, 1) k1_kernel(
    const float* __restrict__ x,
    const float* __restrict__ We1, const float* __restrict__ be1,
    const float* __restrict__ We2, const float* __restrict__ be2,
    const float* __restrict__ We3, const float* __restrict__ be3,
    const float* __restrict__ Wh1, const float* __restrict__ bh1,
    const float* __restrict__ Wh2, const float* __restrict__ bh2,
    const float* __restrict__ Wh3, const float* __restrict__ bh3) {
    float* We1t = sm;                      // 32*96
    float* We2t = We1t + 32 * 96;          // 80*128
    float* We3t = We2t + 80 * 128;         // 104*128
    float* Wh1t = We3t + 104 * 128;
    float* Wh2t = Wh1t + 32 * 96;
    float* Wh3t = Wh2t + 80 * 128;
    float* be1p = Wh3t + 104 * 128;        // 96
    float* be2p = be1p + 96;               // 128
    float* be3p = be2p + 128;              // 128
    float* eb1  = be3p + 128;              // 96
    float* eb2  = eb1 + 96;                // 128
    float* eb3  = eb2 + 128;               // 128
    float* ebn2 = eb3 + 128;               // 4

    loadWt(We1t, We1, 80, 32, 96);
    loadWt(We2t, We2, 104, 80, 128);
    loadWt(We3t, We3, 128, 104, 128);
    loadWt(Wh1t, Wh1, 80, 32, 96);
    loadWt(Wh2t, Wh2, 104, 80, 128);
    loadWt(Wh3t, Wh3, 128, 104, 128);
    loadVec(be1p, be1, 80, 96);
    loadVec(be2p, be2, 104, 128);
    loadVec(be3p, be3, 128, 128);
    loadVec(eb1, bh1, 80, 96);
    loadVec(eb2, bh2, 104, 128);
    loadVec(eb3, bh3, 128, 128);
    __syncthreads();
    const int warp = threadIdx.x >> 5;
    if (warp == 0) expmap_smem<3>(eb1, &ebn2[0]);
    else if (warp == 1) expmap_smem<4>(eb2, &ebn2[1]);
    else if (warp == 2) expmap_smem<4>(eb3, &ebn2[2]);
    __syncthreads();
    const float e1n2 = ebn2[0], e2n2 = ebn2[1], e3n2 = ebn2[2];

    const int lane = threadIdx.x & 31;
    const int b = blockIdx.x;
    const int s0 = warp * T8;

    // load 8 tokens: xs[b, s0+t, c=lane] = x[b, lane, s0+t]
    float xv[1][T8];
    {
        const float* xb = x + b * (32 * 128) + lane * 128 + s0;
        float4 a0 = *(const float4*)(xb);
        float4 a1 = *(const float4*)(xb + 4);
        xv[0][0] = a0.x; xv[0][1] = a0.y; xv[0][2] = a0.z; xv[0][3] = a0.w;
        xv[0][4] = a1.x; xv[0][5] = a1.y; xv[0][6] = a1.z; xv[0][7] = a1.w;
    }

    // ---- Euclidean branch ----
    {
        float h1[3][T8];
        matvec8<32, 96, 3>(We1t, xv, h1);
        addbias_relu8<3>(be1p, h1);
        float h2[4][T8];
        matvec8<80, 128, 4>(We2t, h1, h2);
        addbias_relu8<4>(be2p, h2);
        float h3[4][T8];
        matvec8<104, 128, 4>(We3t, h2, h3);
        addbias_relu8<4>(be3p, h3);
        float* dst = g_oe + (b * SQ + s0) * 128 + lane;
#pragma unroll
        for (int t = 0; t < T8; t++)
#pragma unroll
            for (int r = 0; r < 4; r++) dst[t * 128 + 32 * r] = h3[r][t];
    }

    // ---- Hyperbolic branch ----
    {
        float xh[1][T8];
#pragma unroll
        for (int t = 0; t < T8; t++) xh[0][t] = xv[0][t];
        expmap0_8<1>(xh);
        float y1[3][T8];
        hyp_linear8<32, 96, 3>(Wh1t, eb1, e1n2, xh, y1);
        mobrelu8<3>(y1);
        float y2[4][T8];
        hyp_linear8<80, 128, 4>(Wh2t, eb2, e2n2, y1, y2);
        mobrelu8<4>(y2);
        float y3[4][T8];
        hyp_linear8<104, 128, 4>(Wh3t, eb3, e3n2, y2, y3);
        float* dst = g_oh + (b * SQ + s0) * 128 + lane;
#pragma unroll
        for (int t = 0; t < T8; t++)
#pragma unroll
            for (int r = 0; r < 4; r++) dst[t * 128 + 32 * r] = y3[r][t];
    }
}

// ========== Kernel 2: attention + pooling + classifier (block = batch) ==========
__global__ void __launch_bounds__(512, 1) k2_kernel(
    const float* __restrict__ Wae, const float* __restrict__ bae,
    const float* __restrict__ Wah, const float* __restrict__ bah,
    const float* __restrict__ Wte, const float* __restrict__ bte,
    const float* __restrict__ Wth, const float* __restrict__ bth,
    const float* __restrict__ Wf1, const float* __restrict__ bf1,
    const float* __restrict__ Wf2, const float* __restrict__ bf2,
    float* __restrict__ out) {
    float* Waet = sm;                    // 16384
    float* Waht = Waet + 16384;          // 16384
    float* baep = Waht + 16384;          // 128
    float* ebah = baep + 128;            // 128
    float* Wtes = ebah + 128;            // 128
    float* Wths = Wtes + 128;            // 128
    float* pes  = Wths + 128;            // 16*128
    float* phs  = pes + 2048;            // 16*128
    float* os   = phs + 2048;            // 256
    float* hs   = os + 256;              // 16
    float* scal = hs + 16;               // 4

    loadWt(Waet, Wae, 128, 128, 128);
    loadWt(Waht, Wah, 128, 128, 128);
    loadVec(baep, bae, 128, 128);
    loadVec(ebah, bah, 128, 128);
    loadVec(Wtes, Wte, 128, 128);
    loadVec(Wths, Wth, 128, 128);
    __syncthreads();
    const int warp = threadIdx.x >> 5;
    const int lane = threadIdx.x & 31;
    if (warp == 0) expmap_smem<4>(ebah, &scal[0]);
    __syncthreads();
    const float ebn2 = scal[0];
    const float bte0 = bte[0], bth0 = bth[0];
    const int b = blockIdx.x, s0 = warp * T8;

    float oe[4][T8], oh[4][T8];
    {
        const float* pe_ = g_oe + (b * SQ + s0) * 128 + lane;
        const float* po_ = g_oh + (b * SQ + s0) * 128 + lane;
#pragma unroll
        for (int t = 0; t < T8; t++)
#pragma unroll
            for (int r = 0; r < 4; r++) {
                oe[r][t] = pe_[t * 128 + 32 * r];
                oh[r][t] = po_[t * 128 + 32 * r];
            }
    }

    float te[4][T8];
    matvec8<128, 128, 4>(Waet, oe, te);
    addbias8<4>(baep, te);

    float th[4][T8];
    hyp_linear8<128, 128, 4>(Waht, ebah, ebn2, oh, th);
    logmap0_8<4>(th);

    // attention scores: a_e = Wte.(tan_e - mu) + bte; tan_e - mu = 0.5*(te - th)
    float ae[T8], ah[T8];
    {
        float pa[T8], pb[T8];
#pragma unroll
        for (int t = 0; t < T8; t++) { pa[t] = 0.f; pb[t] = 0.f; }
#pragma unroll
        for (int r = 0; r < 4; r++) {
            float wa = Wtes[lane + 32 * r], wb = Wths[lane + 32 * r];
#pragma unroll
            for (int t = 0; t < T8; t++) {
                float d = 0.5f * (te[r][t] - th[r][t]);
                pa[t] = fmaf(wa, d, pa[t]);
                pb[t] = fmaf(wb, -d, pb[t]);
            }
        }
#pragma unroll
        for (int t = 0; t < T8; t++) {
            ae[t] = wsum(pa[t]) + bte0;
            ah[t] = wsum(pb[t]) + bth0;
        }
    }
    float w0[T8], w1[T8];
#pragma unroll
    for (int t = 0; t < T8; t++) {
        float m = fmaxf(ae[t], ah[t]);
        float e0 = expf(ae[t] - m), e1 = expf(ah[t] - m);
        float inv = 1.f / (e0 + e1);
        w0[t] = e0 * inv;
        w1[t] = e1 * inv;
    }

    float acc_e[4] = {0.f, 0.f, 0.f, 0.f};
#pragma unroll
    for (int r = 0; r < 4; r++)
#pragma unroll
        for (int t = 0; t < T8; t++) acc_e[r] = fmaf(w0[t], oe[r][t], acc_e[r]);

    // p_mobius_scalar_mul(w1, out_h) then logmap0
    float on2[T8];
    sumsq8<4>(oh, on2);
    float sc[T8];
#pragma unroll
    for (int t = 0; t < T8; t++) {
        float n = fmaxf(sqrtf(on2[t]), K_MIN);
        sc[t] = tanhf(fminf(w1[t] * artanh_c(kSQC() * n), 15.f)) / (n * kSQC());
    }
    float phv[4][T8];
#pragma unroll
    for (int r = 0; r < 4; r++)
#pragma unroll
        for (int t = 0; t < T8; t++) phv[r][t] = oh[r][t] * sc[t];
    projx8<4>(phv);
    logmap0_8<4>(phv);
    float acc_h[4] = {0.f, 0.f, 0.f, 0.f};
#pragma unroll
    for (int r = 0; r < 4; r++)
#pragma unroll
        for (int t = 0; t < T8; t++) acc_h[r] += phv[r][t];

#pragma unroll
    for (int r = 0; r < 4; r++) {
        pes[warp * 128 + lane + 32 * r] = acc_e[r];
        phs[warp * 128 + lane + 32 * r] = acc_h[r];
    }
    __syncthreads();

    // reduce 16 warp partials -> pooled o (256), mean over S=128
    for (int j = threadIdx.x; j < 256; j += 512) {
        const float* src = (j < 128) ? (pes + j) : (phs + (j - 128));
        float s = 0.f;
#pragma unroll
        for (int i = 0; i < 16; i++) s += src[i * 128];
        os[j] = s * (1.0f / 128.0f);
    }
    __syncthreads();

    // classifier
    if (threadIdx.x < 32) {
        if (lane < 10) {
            float h = bf1[lane];
            for (int i = 0; i < 256; i++) h = fmaf(Wf1[lane * 256 + i], os[i], h);
            hs[lane] = fmaxf(h, 0.f);
        }
        __syncwarp();
        if (lane < 10) {
            float o2 = bf2[lane];
#pragma unroll
            for (int i = 0; i < 10; i++) o2 = fmaf(Wf2[lane * 10 + i], hs[i], o2);
            out[b * 10 + lane] = o2;
        }
    }
}

extern "C" void kernel_launch(void* const* d_in, const int* in_sizes, int n_in,
                              void* d_out, int out_size) {
    (void)in_sizes; (void)n_in; (void)out_size;
    const float* x   = (const float*)d_in[0];
    const float* We1 = (const float*)d_in[1];  const float* be1 = (const float*)d_in[2];
    const float* We2 = (const float*)d_in[3];  const float* be2 = (const float*)d_in[4];
    const float* We3 = (const float*)d_in[5];  const float* be3 = (const float*)d_in[6];
    const float* Wh1 = (const float*)d_in[7];  const float* bh1 = (const float*)d_in[8];
    const float* Wh2 = (const float*)d_in[9];  const float* bh2 = (const float*)d_in[10];
    const float* Wh3 = (const float*)d_in[11]; const float* bh3 = (const float*)d_in[12];
    const float* Wae = (const float*)d_in[13]; const float* bae = (const float*)d_in[14];
    const float* Wah = (const float*)d_in[15]; const float* bah = (const float*)d_in[16];
    const float* Wte = (const float*)d_in[17]; const float* bte = (const float*)d_in[18];
    const float* Wth = (const float*)d_in[19]; const float* bth = (const float*)d_in[20];
    const float* Wf1 = (const float*)d_in[21]; const float* bf1 = (const float*)d_in[22];
    const float* Wf2 = (const float*)d_in[23]; const float* bf2 = (const float*)d_in[24];
    float* out = (float*)d_out;

    size_t sm1 = (size_t)((32 * 96 + 80 * 128 + 104 * 128) * 2 + 96 + 128 + 128 + 96 + 128 + 128 + 4) * sizeof(float);
    size_t sm2 = (size_t)(16384 * 2 + 128 * 4 + 2048 * 2 + 256 + 16 + 4) * sizeof(float);

    cudaFuncSetAttribute(k1_kernel, cudaFuncAttributeMaxDynamicSharedMemorySize, (int)sm1);
    cudaFuncSetAttribute(k2_kernel, cudaFuncAttributeMaxDynamicSharedMemorySize, (int)sm2);

    k1_kernel<<<NB, 512, sm1>>>(x, We1, be1, We2, be2, We3, be3,
                                Wh1, bh1, Wh2, bh2, Wh3, bh3);
    k2_kernel<<<NB, 512, sm2>>>(Wae, bae, Wah, bah, Wte, bte, Wth, bth,
                                Wf1, bf1, Wf2, bf2, out);
}

// round 2
// speedup vs baseline: 1.2810x; 1.2810x over previous
#include <cuda_runtime.h>

typedef unsigned long long ull;

#define FULLMASK 0xffffffffu
#define NB 1024
#define SQ 128
#define K_C   1.2f
#define K_MIN 1e-15f

__device__ __forceinline__ float kSQC()  { return 1.0954451150103321f; }   // sqrt(1.2)
__device__ __forceinline__ float kMaxN() { return 0.90921944545857576f; }  // (1-4e-3)/sqrt(1.2)

// inter-kernel scratch (no cudaMalloc allowed)
__device__ float g_oe[NB * SQ * 128];
__device__ float g_oh[NB * SQ * 128];
__device__ float g_ohn2[NB * SQ];

// ---------------- packed f32x2 helpers ----------------
__device__ __forceinline__ ull pk2(float a, float b) {
    ull r; asm("mov.b64 %0,{%1,%2};" : "=l"(r) : "f"(a), "f"(b)); return r;
}
__device__ __forceinline__ ull pkd(float a) { return pk2(a, a); }
__device__ __forceinline__ void upk2(ull v, float& a, float& b) {
    asm("mov.b64 {%0,%1},%2;" : "=f"(a), "=f"(b) : "l"(v));
}
__device__ __forceinline__ ull fma2_(ull a, ull b, ull c) {
    ull d; asm("fma.rn.f32x2 %0,%1,%2,%3;" : "=l"(d) : "l"(a), "l"(b), "l"(c)); return d;
}
__device__ __forceinline__ ull add2_(ull a, ull b) {
    ull d; asm("add.rn.f32x2 %0,%1,%2;" : "=l"(d) : "l"(a), "l"(b)); return d;
}
__device__ __forceinline__ ull mul2_(ull a, ull b) {
    ull d; asm("mul.rn.f32x2 %0,%1,%2;" : "=l"(d) : "l"(a), "l"(b)); return d;
}

__device__ __forceinline__ float wsum(float v) {
    v += __shfl_xor_sync(FULLMASK, v, 16);
    v += __shfl_xor_sync(FULLMASK, v, 8);
    v += __shfl_xor_sync(FULLMASK, v, 4);
    v += __shfl_xor_sync(FULLMASK, v, 2);
    v += __shfl_xor_sync(FULLMASK, v, 1);
    return v;
}
__device__ __forceinline__ ull wsum2(ull v) {
    v = add2_(v, __shfl_xor_sync(FULLMASK, v, 16));
    v = add2_(v, __shfl_xor_sync(FULLMASK, v, 8));
    v = add2_(v, __shfl_xor_sync(FULLMASK, v, 4));
    v = add2_(v, __shfl_xor_sync(FULLMASK, v, 2));
    v = add2_(v, __shfl_xor_sync(FULLMASK, v, 1));
    return v;
}

__device__ __forceinline__ float artanh_c(float z) {
    z = fminf(z, 1.0f - 1e-7f);
    return 0.5f * logf((1.0f + z) / (1.0f - z));
}

// ------- packed warp-tiled matvec: 8 tokens as 4 f32x2 pairs -------
// Wt: K x (32R) transposed weights in smem. xb: per-warp activation buffer,
// stride 5 ull per k (conflict-free). acc[r][p]: j=lane+32r, tokens (2p,2p+1).
template<int K, int R>
__device__ __forceinline__ void mv2(const float* __restrict__ Wt,
                                    const ull* __restrict__ xb,
                                    ull (&acc)[R][4]) {
    const int lane = threadIdx.x & 31;
#pragma unroll
    for (int r = 0; r < R; r++)
#pragma unroll
        for (int p = 0; p < 4; p++) acc[r][p] = 0ull;
    const float* w = Wt + lane;
    const ull* xp = xb;
#pragma unroll 4
    for (int k = 0; k < K; k++) {
        ull x0 = xp[0], x1 = xp[1], x2 = xp[2], x3 = xp[3];
#pragma unroll
        for (int r = 0; r < R; r++) {
            ull wd = pkd(w[32 * r]);
            acc[r][0] = fma2_(wd, x0, acc[r][0]);
            acc[r][1] = fma2_(wd, x1, acc[r][1]);
            acc[r][2] = fma2_(wd, x2, acc[r][2]);
            acc[r][3] = fma2_(wd, x3, acc[r][3]);
        }
        w += 32 * R;
        xp += 5;
    }
}

template<int R>
__device__ __forceinline__ void ssq2(const ull (&v)[R][4], float (&o)[8]) {
#pragma unroll
    for (int p = 0; p < 4; p++) {
        ull a = 0ull;
#pragma unroll
        for (int r = 0; r < R; r++) a = fma2_(v[r][p], v[r][p], a);
        a = wsum2(a);
        upk2(a, o[2 * p], o[2 * p + 1]);
    }
}

template<int R>
__device__ __forceinline__ void scale2(ull (&v)[R][4], const float (&s)[8]) {
    ull sp[4];
#pragma unroll
    for (int p = 0; p < 4; p++) sp[p] = pk2(s[2 * p], s[2 * p + 1]);
#pragma unroll
    for (int r = 0; r < R; r++)
#pragma unroll
        for (int p = 0; p < 4; p++) v[r][p] = mul2_(v[r][p], sp[p]);
}

template<int R>
__device__ __forceinline__ void put2(ull* xb, const ull (&v)[R][4]) {
    const int lane = threadIdx.x & 31;
#pragma unroll
    for (int r = 0; r < R; r++) {
        ull* d = xb + (lane + 32 * r) * 5;
#pragma unroll
        for (int p = 0; p < 4; p++) d[p] = v[r][p];
    }
}

// expmap0 on packed regs, with analytic out-norm^2 carried
template<int R>
__device__ __forceinline__ void expmap2(ull (&v)[R][4], float (&xn2)[8]) {
    float s2[8];
    ssq2<R>(v, s2);
    float f[8];
#pragma unroll
    for (int t = 0; t < 8; t++) {
        float n = fmaxf(sqrtf(s2[t]), K_MIN);
        float tt = tanhf(fminf(kSQC() * n, 15.f));
        float e = tt / (kSQC() * n);
        float ny = tt / kSQC();
        float pg = (ny > kMaxN()) ? (kMaxN() / ny) : 1.f;
        f[t] = e * pg;
        ny = fminf(ny, kMaxN());
        xn2[t] = ny * ny;
    }
    scale2<R>(v, f);
}

// p_linear (PoincareBall) core: out = mobius_add(projx(mobius_matvec(W,x)), eb)
// (final projx NOT applied here; caller folds it with the next op).
// on2raw = ||out||^2 before final projx. xn2 = input norm^2 (carried).
template<int K, int R>
__device__ __forceinline__ void hyplin2(const float* __restrict__ Wt,
                                        const float* __restrict__ eb, float ebn2,
                                        const ull* __restrict__ xb,
                                        const float (&xn2)[8],
                                        ull (&out)[R][4], float (&on2raw)[8]) {
    const int lane = threadIdx.x & 31;
    mv2<K, R>(Wt, xb, out);
    float mn2[8];
    ssq2<R>(out, mn2);
    float tot[8], x2[8];
#pragma unroll
    for (int t = 0; t < 8; t++) {
        float xn = fmaxf(sqrtf(xn2[t]), K_MIN);
        float mn = fmaxf(sqrtf(mn2[t]), K_MIN);
        float ar = artanh_c(kSQC() * xn);
        float tt = tanhf(fminf(mn / xn * ar, 15.f));
        float sc = (mn2[t] == 0.f) ? 0.f : tt / (mn * kSQC());
        float nr = (mn2[t] == 0.f) ? 0.f : tt / kSQC();
        float g = (nr > kMaxN()) ? (kMaxN() / nr) : 1.f;
        tot[t] = sc * g;
        nr = fminf(nr, kMaxN());
        x2[t] = nr * nr;
    }
    scale2<R>(out, tot);
    // xy = <out, eb>
    float xy[8];
    {
        ull dp[4] = {0ull, 0ull, 0ull, 0ull};
#pragma unroll
        for (int r = 0; r < R; r++) {
            ull ed = pkd(eb[lane + 32 * r]);
#pragma unroll
            for (int p = 0; p < 4; p++) dp[p] = fma2_(out[r][p], ed, dp[p]);
        }
#pragma unroll
        for (int p = 0; p < 4; p++) {
            ull a = wsum2(dp[p]);
            upk2(a, xy[2 * p], xy[2 * p + 1]);
        }
    }
    ull ca[4], cb[4], iv[4];
#pragma unroll
    for (int p = 0; p < 4; p++) {
        float c0[2], c1[2], c2[2];
#pragma unroll
        for (int h = 0; h < 2; h++) {
            int t = 2 * p + h;
            float a = 1.f + 2.f * K_C * xy[t] + K_C * ebn2;
            float b = 1.f - K_C * x2[t];
            float dn = 1.f + 2.f * K_C * xy[t] + K_C * K_C * x2[t] * ebn2;
            c0[h] = a; c1[h] = b; c2[h] = 1.f / fmaxf(dn, K_MIN);
        }
        ca[p] = pk2(c0[0], c0[1]);
        cb[p] = pk2(c1[0], c1[1]);
        iv[p] = pk2(c2[0], c2[1]);
    }
#pragma unroll
    for (int r = 0; r < R; r++) {
        ull ed = pkd(eb[lane + 32 * r]);
#pragma unroll
        for (int p = 0; p < 4; p++)
            out[r][p] = mul2_(fma2_(ca[p], out[r][p], mul2_(cb[p], ed)), iv[p]);
    }
    ssq2<R>(out, on2raw);
}

// Mob_Act(relu): fold trailing projx of p_linear + logmap0, relu, expmap0(+projx)
template<int R>
__device__ __forceinline__ void mobrelu2(ull (&v)[R][4], const float (&on2raw)[8],
                                         float (&xn2n)[8]) {
    float f[8];
#pragma unroll
    for (int t = 0; t < 8; t++) {
        float n = fmaxf(sqrtf(on2raw[t]), K_MIN);
        float pf = (n > kMaxN()) ? (kMaxN() / n) : 1.f;
        float nc = fminf(n, kMaxN());
        float ls = artanh_c(kSQC() * nc) / (kSQC() * nc);
        f[t] = pf * ls;
    }
    // apply f, relu, accumulate squares
    ull sp[4] = {0ull, 0ull, 0ull, 0ull};
#pragma unroll
    for (int p = 0; p < 4; p++) {
        ull fp = pk2(f[2 * p], f[2 * p + 1]);
#pragma unroll
        for (int r = 0; r < R; r++) {
            ull w = mul2_(v[r][p], fp);
            float a, b;
            upk2(w, a, b);
            a = fmaxf(a, 0.f);
            b = fmaxf(b, 0.f);
            w = pk2(a, b);
            v[r][p] = w;
            sp[p] = fma2_(w, w, sp[p]);
        }
    }
    float s2[8];
#pragma unroll
    for (int p = 0; p < 4; p++) {
        ull a = wsum2(sp[p]);
        upk2(a, s2[2 * p], s2[2 * p + 1]);
    }
#pragma unroll
    for (int t = 0; t < 8; t++) {
        float n = fmaxf(sqrtf(s2[t]), K_MIN);
        float tt = tanhf(fminf(kSQC() * n, 15.f));
        float e = tt / (kSQC() * n);
        float ny = tt / kSQC();
        float pg = (ny > kMaxN()) ? (kMaxN() / ny) : 1.f;
        f[t] = e * pg;
        ny = fminf(ny, kMaxN());
        xn2n[t] = ny * ny;
    }
    scale2<R>(v, f);
}

// ---- cooperative smem loaders ----
__device__ __forceinline__ void loadWt(float* dst, const float* __restrict__ W,
                                       int J, int K, int Jpad) {
    int n = K * Jpad;
    for (int i = threadIdx.x; i < n; i += blockDim.x) {
        int k = i / Jpad;
        int j = i - k * Jpad;
        dst[i] = (j < J) ? W[j * K + k] : 0.f;
    }
}
__device__ __forceinline__ void loadVec(float* dst, const float* __restrict__ v, int J, int Jpad) {
    for (int i = threadIdx.x; i < Jpad; i += blockDim.x) dst[i] = (i < J) ? v[i] : 0.f;
}

// warp-level expmap0 of a bias vector in smem (padded), also stores ||eb||^2
template<int R>
__device__ __forceinline__ void expmap_smem(float* v, float* n2out) {
    const int lane = threadIdx.x & 31;
    float a[R];
    float p = 0.f;
#pragma unroll
    for (int r = 0; r < R; r++) {
        a[r] = v[lane + 32 * r];
        p = fmaf(a[r], a[r], p);
    }
    p = wsum(p);
    float n = fmaxf(sqrtf(p), K_MIN);
    float tt = tanhf(fminf(kSQC() * n, 15.f));
    float scv = tt / (kSQC() * n);
#pragma unroll
    for (int r = 0; r < R; r++) a[r] *= scv;
    float q = 0.f;
#pragma unroll
    for (int r = 0; r < R; r++) q = fmaf(a[r], a[r], q);
    q = wsum(q);
    float nn = fmaxf(sqrtf(q), K_MIN);
    if (nn > kMaxN()) {
        float fsc = kMaxN() / nn;
#pragma unroll
        for (int r = 0; r < R; r++) a[r] *= fsc;
    }
    float y2 = 0.f;
#pragma unroll
    for (int r = 0; r < R; r++) y2 = fmaf(a[r], a[r], y2);
    y2 = wsum(y2);
#pragma unroll
    for (int r = 0; r < R; r++) v[lane + 32 * r] = a[r];
    if (lane == 0) *n2out = y2;
}

extern __shared__ float sm[];

// ================= Kernel E: Euclidean branch =================
// smem: We1t(3072) We2t(10240) We3t(13312) be1p(96) be2p(128) be3p(128) xbuf(20480)
#define KE_XOFF 26976
__global__ void __launch_bounds__(512) kE_kernel(
    const float* __restrict__ x,
    const float* __restrict__ We1, const float* __restrict__ be1,
    const float* __restrict__ We2, const float* __restrict__ be2,
    const float* __restrict__ We3, const float* __restrict__ be3) {
    float* We1t = sm;
    float* We2t = We1t + 3072;
    float* We3t = We2t + 10240;
    float* be1p = We3t + 13312;
    float* be2p = be1p + 96;
    float* be3p = be2p + 128;

    loadWt(We1t, We1, 80, 32, 96);
    loadWt(We2t, We2, 104, 80, 128);
    loadWt(We3t, We3, 128, 104, 128);
    loadVec(be1p, be1, 80, 96);
    loadVec(be2p, be2, 104, 128);
    loadVec(be3p, be3, 128, 128);
    __syncthreads();

    const int lane = threadIdx.x & 31;
    const int warp = threadIdx.x >> 5;
    const int b = blockIdx.x;
    const int s0 = warp * 8;
    ull* xb = (ull*)(sm + KE_XOFF) + warp * 640;

    // stage input x: xs[b, s, k=lane] = x[b, lane, s], 8 contiguous tokens
    {
        const float* xsrc = x + b * (32 * 128) + lane * 128 + s0;
        float4 a0 = *(const float4*)(xsrc);
        float4 a1 = *(const float4*)(xsrc + 4);
        ull* d = xb + lane * 5;
        d[0] = pk2(a0.x, a0.y);
        d[1] = pk2(a0.z, a0.w);
        d[2] = pk2(a1.x, a1.y);
        d[3] = pk2(a1.z, a1.w);
    }
    __syncwarp();

    ull h1[3][4];
    mv2<32, 3>(We1t, xb, h1);
#pragma unroll
    for (int r = 0; r < 3; r++) {
        float bv = be1p[lane + 32 * r];
#pragma unroll
        for (int p = 0; p < 4; p++) {
            float a, c;
            upk2(h1[r][p], a, c);
            h1[r][p] = pk2(fmaxf(a + bv, 0.f), fmaxf(c + bv, 0.f));
        }
    }
    __syncwarp();
    put2<3>(xb, h1);
    __syncwarp();

    ull h2[4][4];
    mv2<80, 4>(We2t, xb, h2);
#pragma unroll
    for (int r = 0; r < 4; r++) {
        float bv = be2p[lane + 32 * r];
#pragma unroll
        for (int p = 0; p < 4; p++) {
            float a, c;
            upk2(h2[r][p], a, c);
            h2[r][p] = pk2(fmaxf(a + bv, 0.f), fmaxf(c + bv, 0.f));
        }
    }
    __syncwarp();
    put2<4>(xb, h2);
    __syncwarp();

    ull h3[4][4];
    mv2<104, 4>(We3t, xb, h3);
    float* dst = g_oe + (b * SQ + s0) * 128 + lane;
#pragma unroll
    for (int r = 0; r < 4; r++) {
        float bv = be3p[lane + 32 * r];
#pragma unroll
        for (int p = 0; p < 4; p++) {
            float a, c;
            upk2(h3[r][p], a, c);
            dst[(2 * p) * 128 + 32 * r] = fmaxf(a + bv, 0.f);
            dst[(2 * p + 1) * 128 + 32 * r] = fmaxf(c + bv, 0.f);
        }
    }
}

// ================= Kernel H: hyperbolic branch =================
#define KH_XOFF 26980
__global__ void __launch_bounds__(512) kH_kernel(
    const float* __restrict__ x,
    const float* __restrict__ Wh1, const float* __restrict__ bh1,
    const float* __restrict__ Wh2, const float* __restrict__ bh2,
    const float* __restrict__ Wh3, const float* __restrict__ bh3) {
    float* Wh1t = sm;
    float* Wh2t = Wh1t + 3072;
    float* Wh3t = Wh2t + 10240;
    float* eb1 = Wh3t + 13312;   // 96
    float* eb2 = eb1 + 96;       // 128
    float* eb3 = eb2 + 128;      // 128
    float* ebn2 = eb3 + 128;     // 4

    loadWt(Wh1t, Wh1, 80, 32, 96);
    loadWt(Wh2t, Wh2, 104, 80, 128);
    loadWt(Wh3t, Wh3, 128, 104, 128);
    loadVec(eb1, bh1, 80, 96);
    loadVec(eb2, bh2, 104, 128);
    loadVec(eb3, bh3, 128, 128);
    __syncthreads();
    const int warp = threadIdx.x >> 5;
    if (warp == 0) expmap_smem<3>(eb1, &ebn2[0]);
    else if (warp == 1) expmap_smem<4>(eb2, &ebn2[1]);
    else if (warp == 2) expmap_smem<4>(eb3, &ebn2[2]);
    __syncthreads();
    const float e1n2 = ebn2[0], e2n2 = ebn2[1], e3n2 = ebn2[2];

    const int lane = threadIdx.x & 31;
    const int b = blockIdx.x;
    const int s0 = warp * 8;
    ull* xb = (ull*)(sm + KH_XOFF) + warp * 640;

    // stage x and expmap0
    ull xh[1][4];
    {
        const float* xsrc = x + b * (32 * 128) + lane * 128 + s0;
        float4 a0 = *(const float4*)(xsrc);
        float4 a1 = *(const float4*)(xsrc + 4);
        xh[0][0] = pk2(a0.x, a0.y);
        xh[0][1] = pk2(a0.z, a0.w);
        xh[0][2] = pk2(a1.x, a1.y);
        xh[0][3] = pk2(a1.z, a1.w);
    }
    float xn2[8];
    expmap2<1>(xh, xn2);
    __syncwarp();
    put2<1>(xb, xh);
    __syncwarp();

    ull y1[3][4];
    float on2[8];
    hyplin2<32, 3>(Wh1t, eb1, e1n2, xb, xn2, y1, on2);
    mobrelu2<3>(y1, on2, xn2);
    __syncwarp();
    put2<3>(xb, y1);
    __syncwarp();

    ull y2[4][4];
    hyplin2<80, 4>(Wh2t, eb2, e2n2, xb, xn2, y2, on2);
    mobrelu2<4>(y2, on2, xn2);
    __syncwarp();
    put2<4>(xb, y2);
    __syncwarp();

    ull y3[4][4];
    hyplin2<104, 4>(Wh3t, eb3, e3n2, xb, xn2, y3, on2);
    // final projx (analytic) + store vector and norm^2
    float pf[8], nn[8];
#pragma unroll
    for (int t = 0; t < 8; t++) {
        float n = fmaxf(sqrtf(on2[t]), K_MIN);
        pf[t] = (n > kMaxN()) ? (kMaxN() / n) : 1.f;
        float nc = fminf(n, kMaxN());
        nn[t] = nc * nc;
    }
    float* dst = g_oh + (b * SQ + s0) * 128 + lane;
#pragma unroll
    for (int r = 0; r < 4; r++)
#pragma unroll
        for (int p = 0; p < 4; p++) {
            float a, c;
            upk2(y3[r][p], a, c);
            dst[(2 * p) * 128 + 32 * r] = a * pf[2 * p];
            dst[(2 * p + 1) * 128 + 32 * r] = c * pf[2 * p + 1];
        }
#pragma unroll
    for (int t = 0; t < 8; t++)
        if (lane == t) g_ohn2[b * SQ + s0 + t] = nn[t];
}

// ========== Kernel 2: attention + pooling + classifier ==========
// smem: Waet(16384) Waht(16384) baep(128) ebah(128) Wtes(128) Wths(128) scal(4) os(256) hs(16) xbuf(20480)
#define K2_XOFF 33556
__global__ void __launch_bounds__(512) k2_kernel(
    const float* __restrict__ Wae, const float* __restrict__ bae,
    const float* __restrict__ Wah, const float* __restrict__ bah,
    const float* __restrict__ Wte, const float* __restrict__ bte,
    const float* __restrict__ Wth, const float* __restrict__ bth,
    const float* __restrict__ Wf1, const float* __restrict__ bf1,
    const float* __restrict__ Wf2, const float* __restrict__ bf2,
    float* __restrict__ out) {
    float* Waet = sm;
    float* Waht = Waet + 16384;
    float* baep = Waht + 16384;
    float* ebah = baep + 128;
    float* Wtes = ebah + 128;
    float* Wths = Wtes + 128;
    float* scal = Wths + 128;   // 4
    float* os = scal + 4;       // 256
    float* hs = os + 256;       // 16

    loadWt(Waet, Wae, 128, 128, 128);
    loadWt(Waht, Wah, 128, 128, 128);
    loadVec(baep, bae, 128, 128);
    loadVec(ebah, bah, 128, 128);
    loadVec(Wtes, Wte, 128, 128);
    loadVec(Wths, Wth, 128, 128);
    __syncthreads();
    const int warp = threadIdx.x >> 5;
    const int lane = threadIdx.x & 31;
    if (warp == 0) expmap_smem<4>(ebah, &scal[0]);
    __syncthreads();
    const float ebn2 = scal[0];
    const float bte0 = bte[0], bth0 = bth[0];
    const int b = blockIdx.x, s0 = warp * 8;
    ull* xb = (ull*)(sm + K2_XOFF) + warp * 640;

    // ---- stage oe, compute tan_e ----
    {
        const float* src = g_oe + (b * SQ + s0) * 128;
#pragma unroll
        for (int r = 0; r < 4; r++) {
            int k = lane + 32 * r;
            float v[8];
#pragma unroll
            for (int t = 0; t < 8; t++) v[t] = src[t * 128 + k];
            ull* d = xb + k * 5;
#pragma unroll
            for (int p = 0; p < 4; p++) d[p] = pk2(v[2 * p], v[2 * p + 1]);
        }
    }
    __syncwarp();
    ull te[4][4];
    mv2<128, 4>(Waet, xb, te);
#pragma unroll
    for (int r = 0; r < 4; r++) {
        ull bv = pkd(baep[lane + 32 * r]);
#pragma unroll
        for (int p = 0; p < 4; p++) te[r][p] = add2_(te[r][p], bv);
    }
    __syncwarp();

    // ---- stage oh (keep regs), compute tan_h ----
    ull ohreg[4][4];
    {
        const float* src = g_oh + (b * SQ + s0) * 128;
#pragma unroll
        for (int r = 0; r < 4; r++) {
            int k = lane + 32 * r;
            float v[8];
#pragma unroll
            for (int t = 0; t < 8; t++) v[t] = src[t * 128 + k];
            ull* d = xb + k * 5;
#pragma unroll
            for (int p = 0; p < 4; p++) {
                ull pv = pk2(v[2 * p], v[2 * p + 1]);
                d[p] = pv;
                ohreg[r][p] = pv;
            }
        }
    }
    float xn2[8];
#pragma unroll
    for (int t = 0; t < 8; t++) xn2[t] = g_ohn2[b * SQ + s0 + t];
    __syncwarp();

    ull th[4][4];
    float on2[8];
    hyplin2<128, 4>(Waht, ebah, ebn2, xb, xn2, th, on2);
    // fold projx + logmap0
    {
        float f[8];
#pragma unroll
        for (int t = 0; t < 8; t++) {
            float n = fmaxf(sqrtf(on2[t]), K_MIN);
            float pf = (n > kMaxN()) ? (kMaxN() / n) : 1.f;
            float nc = fminf(n, kMaxN());
            float ls = artanh_c(kSQC() * nc) / (kSQC() * nc);
            f[t] = pf * ls;
        }
        scale2<4>(th, f);
    }

    // ---- attention scores ----
    float ae[8], ah[8];
    {
        ull pa[4] = {0ull, 0ull, 0ull, 0ull};
        ull pb[4] = {0ull, 0ull, 0ull, 0ull};
        const ull hp = pkd(0.5f), hn = pkd(-0.5f);
#pragma unroll
        for (int r = 0; r < 4; r++) {
            ull wa = pkd(Wtes[lane + 32 * r]);
            ull wb = pkd(Wths[lane + 32 * r]);
#pragma unroll
            for (int p = 0; p < 4; p++) {
                ull d = fma2_(te[r][p], hp, mul2_(th[r][p], hn));
                pa[p] = fma2_(wa, d, pa[p]);
                pb[p] = fma2_(wb, d, pb[p]);
            }
        }
#pragma unroll
        for (int p = 0; p < 4; p++) {
            ull a = wsum2(pa[p]);
            ull c = wsum2(pb[p]);
            float a0, a1, c0, c1;
            upk2(a, a0, a1);
            upk2(c, c0, c1);
            ae[2 * p] = a0 + bte0;
            ae[2 * p + 1] = a1 + bte0;
            ah[2 * p] = bth0 - c0;
            ah[2 * p + 1] = bth0 - c1;
        }
    }
    float w0[8], w1[8];
#pragma unroll
    for (int t = 0; t < 8; t++) {
        float m = fmaxf(ae[t], ah[t]);
        float e0 = expf(ae[t] - m), e1 = expf(ah[t] - m);
        float inv = 1.f / (e0 + e1);
        w0[t] = e0 * inv;
        w1[t] = e1 * inv;
    }

    // ---- proc_e = w0 * out_e (reload oe), pool ----
    float acce[4];
    {
        const float* pe = g_oe + (b * SQ + s0) * 128 + lane;
#pragma unroll
        for (int r = 0; r < 4; r++) {
            float s = 0.f;
#pragma unroll
            for (int t = 0; t < 8; t++) s = fmaf(w0[t], pe[t * 128 + 32 * r], s);
            acce[r] = s;
        }
    }

    // ---- proc_h = logmap0(projx(mobius_scalar_mul(w1, out_h))) , pool ----
    float acch[4];
    {
        float tt[8];
#pragma unroll
        for (int t = 0; t < 8; t++) {
            float n = fmaxf(sqrtf(xn2[t]), K_MIN);
            float ar = artanh_c(kSQC() * n);
            float q = tanhf(fminf(w1[t] * ar, 15.f));
            float sc = q / (n * kSQC());
            float qn = q / kSQC();
            float pg = (qn > kMaxN()) ? (kMaxN() / qn) : 1.f;
            float qc = fmaxf(fminf(qn, kMaxN()), K_MIN);
            float ls = artanh_c(kSQC() * qc) / (kSQC() * qc);
            tt[t] = sc * pg * ls;
        }
#pragma unroll
        for (int r = 0; r < 4; r++) {
            ull a = 0ull;
#pragma unroll
            for (int p = 0; p < 4; p++)
                a = fma2_(pk2(tt[2 * p], tt[2 * p + 1]), ohreg[r][p], a);
            float x0, x1;
            upk2(a, x0, x1);
            acch[r] = x0 + x1;
        }
    }

    // partials into the (now-dead) xbuf region
    float* pes = sm + K2_XOFF;          // 2048 floats
    float* phs = pes + 2048;            // 2048 floats
    __syncthreads();
#pragma unroll
    for (int r = 0; r < 4; r++) {
        pes[warp * 128 + lane + 32 * r] = acce[r];
        phs[warp * 128 + lane + 32 * r] = acch[r];
    }
    __syncthreads();

    for (int j = threadIdx.x; j < 256; j += 512) {
        const float* src = (j < 128) ? (pes + j) : (phs + (j - 128));
        float s = 0.f;
#pragma unroll
        for (int i = 0; i < 16; i++) s += src[i * 128];
        os[j] = s * (1.0f / 128.0f);
    }
    __syncthreads();

    if (threadIdx.x < 32) {
        if (lane < 10) {
            float h = bf1[lane];
            for (int i = 0; i < 256; i++) h = fmaf(Wf1[lane * 256 + i], os[i], h);
            hs[lane] = fmaxf(h, 0.f);
        }
        __syncwarp();
        if (lane < 10) {
            float o2 = bf2[lane];
#pragma unroll
            for (int i = 0; i < 10; i++) o2 = fmaf(Wf2[lane * 10 + i], hs[i], o2);
            out[b * 10 + lane] = o2;
        }
    }
}

extern "C" void kernel_launch(void* const* d_in, const int* in_sizes, int n_in,
                              void* d_out, int out_size) {
    (void)in_sizes; (void)n_in; (void)out_size;
    const float* x   = (const float*)d_in[0];
    const float* We1 = (const float*)d_in[1];  const float* be1 = (const float*)d_in[2];
    const float* We2 = (const float*)d_in[3];  const float* be2 = (const float*)d_in[4];
    const float* We3 = (const float*)d_in[5];  const float* be3 = (const float*)d_in[6];
    const float* Wh1 = (const float*)d_in[7];  const float* bh1 = (const float*)d_in[8];
    const float* Wh2 = (const float*)d_in[9];  const float* bh2 = (const float*)d_in[10];
    const float* Wh3 = (const float*)d_in[11]; const float* bh3 = (const float*)d_in[12];
    const float* Wae = (const float*)d_in[13]; const float* bae = (const float*)d_in[14];
    const float* Wah = (const float*)d_in[15]; const float* bah = (const float*)d_in[16];
    const float* Wte = (const float*)d_in[17]; const float* bte = (const float*)d_in[18];
    const float* Wth = (const float*)d_in[19]; const float* bth = (const float*)d_in[20];
    const float* Wf1 = (const float*)d_in[21]; const float* bf1 = (const float*)d_in[22];
    const float* Wf2 = (const float*)d_in[23]; const float* bf2 = (const float*)d_in[24];
    float* out = (float*)d_out;

    size_t smE = (size_t)(KE_XOFF + 16 * 640 * 2) * sizeof(float);
    size_t smH = (size_t)(KH_XOFF + 16 * 640 * 2) * sizeof(float);
    size_t sm2 = (size_t)(K2_XOFF + 16 * 640 * 2) * sizeof(float);

    static int inited = 0;
    cudaFuncSetAttribute(kE_kernel, cudaFuncAttributeMaxDynamicSharedMemorySize, (int)smE);
    cudaFuncSetAttribute(kH_kernel, cudaFuncAttributeMaxDynamicSharedMemorySize, (int)smH);
    cudaFuncSetAttribute(k2_kernel, cudaFuncAttributeMaxDynamicSharedMemorySize, (int)sm2);
    (void)inited;

    kE_kernel<<<NB, 512, smE>>>(x, We1, be1, We2, be2, We3, be3);
    kH_kernel<<<NB, 512, smH>>>(x, Wh1, bh1, Wh2, bh2, Wh3, bh3);
    k2_kernel<<<NB, 512, sm2>>>(Wae, bae, Wah, bah, Wte, bte, Wth, bth,
                                Wf1, bf1, Wf2, bf2, out);
}

// round 4
// speedup vs baseline: 1.8427x; 1.4385x over previous
#include <cuda_runtime.h>

typedef unsigned long long ull;

#define FULLMASK 0xffffffffu
#define NB 1024
#define SQ 128
#define K_C   1.2f
#define K_MIN 1e-15f
#define XS 6      // ull stride per k-row in the activation buffer (48B, 16B-aligned)
#define XBW 768   // ull per warp activation buffer = 128 rows * XS

__device__ __forceinline__ float kSQC()   { return 1.0954451150103321f; }   // sqrt(1.2)
__device__ __forceinline__ float kISQC()  { return 0.9128709291752769f; }   // 1/sqrt(1.2)
__device__ __forceinline__ float kMaxN()  { return 0.90921944545857576f; }  // (1-4e-3)/sqrt(1.2)
__device__ __forceinline__ float kIMaxN() { return 1.0998446018140677f; }   // 1/kMaxN

// inter-kernel scratch (no cudaMalloc allowed)
__device__ float g_oe[NB * SQ * 128];
__device__ float g_oh[NB * SQ * 128];
__device__ float g_ohn2[NB * SQ];

// ---------------- packed f32x2 helpers ----------------
__device__ __forceinline__ ull pk2(float a, float b) {
    ull r; asm("mov.b64 %0,{%1,%2};" : "=l"(r) : "f"(a), "f"(b)); return r;
}
__device__ __forceinline__ ull pkd(float a) { return pk2(a, a); }
__device__ __forceinline__ void upk2(ull v, float& a, float& b) {
    asm("mov.b64 {%0,%1},%2;" : "=f"(a), "=f"(b) : "l"(v));
}
__device__ __forceinline__ ull fma2_(ull a, ull b, ull c) {
    ull d; asm("fma.rn.f32x2 %0,%1,%2,%3;" : "=l"(d) : "l"(a), "l"(b), "l"(c)); return d;
}
__device__ __forceinline__ ull add2_(ull a, ull b) {
    ull d; asm("add.rn.f32x2 %0,%1,%2;" : "=l"(d) : "l"(a), "l"(b)); return d;
}
__device__ __forceinline__ ull mul2_(ull a, ull b) {
    ull d; asm("mul.rn.f32x2 %0,%1,%2;" : "=l"(d) : "l"(a), "l"(b)); return d;
}

__device__ __forceinline__ float wsum(float v) {
    v += __shfl_xor_sync(FULLMASK, v, 16);
    v += __shfl_xor_sync(FULLMASK, v, 8);
    v += __shfl_xor_sync(FULLMASK, v, 4);
    v += __shfl_xor_sync(FULLMASK, v, 2);
    v += __shfl_xor_sync(FULLMASK, v, 1);
    return v;
}
__device__ __forceinline__ ull wsum2(ull v) {
    v = add2_(v, __shfl_xor_sync(FULLMASK, v, 16));
    v = add2_(v, __shfl_xor_sync(FULLMASK, v, 8));
    v = add2_(v, __shfl_xor_sync(FULLMASK, v, 4));
    v = add2_(v, __shfl_xor_sync(FULLMASK, v, 2));
    v = add2_(v, __shfl_xor_sync(FULLMASK, v, 1));
    return v;
}

__device__ __forceinline__ float artanh_c(float z) {
    z = fminf(z, 1.0f - 1e-7f);
    return 0.5f * __logf(__fdividef(1.0f + z, 1.0f - z));
}
__device__ __forceinline__ float rnorm_c(float s2) {   // 1/max(sqrt(s2),~0)
    return rsqrtf(fmaxf(s2, 1e-30f));
}

// ------- vectorized warp-tiled matvec: 8 tokens as 4 f32x2 pairs -------
// Wc: column-major-per-output weights: Wc[j*SW + k], SW ≡ 4 (mod 8) floats.
// xb: per-warp activation buffer, stride XS ull per k.
template<int K, int SW, int R>
__device__ __forceinline__ void mvv(const float* __restrict__ Wc,
                                    const ull* __restrict__ xb,
                                    ull (&acc)[R][4]) {
    const int lane = threadIdx.x & 31;
#pragma unroll
    for (int r = 0; r < R; r++)
#pragma unroll
        for (int p = 0; p < 4; p++) acc[r][p] = 0ull;
    const float* wp = Wc + lane * SW;
#pragma unroll 4
    for (int k0 = 0; k0 < K; k0 += 4) {
        float4 wv[R];
#pragma unroll
        for (int r = 0; r < R; r++)
            wv[r] = *(const float4*)(wp + r * 32 * SW + k0);
#pragma unroll
        for (int kk = 0; kk < 4; kk++) {
            const ull* xr = xb + (k0 + kk) * XS;
            ulonglong2 xa = *(const ulonglong2*)(xr);
            ulonglong2 xc = *(const ulonglong2*)(xr + 2);
#pragma unroll
            for (int r = 0; r < R; r++) {
                float w = (kk == 0) ? wv[r].x : (kk == 1) ? wv[r].y
                        : (kk == 2) ? wv[r].z : wv[r].w;
                ull wd = pkd(w);
                acc[r][0] = fma2_(wd, xa.x, acc[r][0]);
                acc[r][1] = fma2_(wd, xa.y, acc[r][1]);
                acc[r][2] = fma2_(wd, xc.x, acc[r][2]);
                acc[r][3] = fma2_(wd, xc.y, acc[r][3]);
            }
        }
    }
}

template<int R>
__device__ __forceinline__ void ssq2(const ull (&v)[R][4], float (&o)[8]) {
#pragma unroll
    for (int p = 0; p < 4; p++) {
        ull a = 0ull;
#pragma unroll
        for (int r = 0; r < R; r++) a = fma2_(v[r][p], v[r][p], a);
        a = wsum2(a);
        upk2(a, o[2 * p], o[2 * p + 1]);
    }
}

template<int R>
__device__ __forceinline__ void scale2(ull (&v)[R][4], const float (&s)[8]) {
    ull sp[4];
#pragma unroll
    for (int p = 0; p < 4; p++) sp[p] = pk2(s[2 * p], s[2 * p + 1]);
#pragma unroll
    for (int r = 0; r < R; r++)
#pragma unroll
        for (int p = 0; p < 4; p++) v[r][p] = mul2_(v[r][p], sp[p]);
}

template<int R>
__device__ __forceinline__ void put2(ull* xb, const ull (&v)[R][4]) {
    const int lane = threadIdx.x & 31;
#pragma unroll
    for (int r = 0; r < R; r++) {
        ull* d = xb + (lane + 32 * r) * XS;
        ulonglong2 a; a.x = v[r][0]; a.y = v[r][1];
        ulonglong2 c; c.x = v[r][2]; c.y = v[r][3];
        *(ulonglong2*)(d) = a;
        *(ulonglong2*)(d + 2) = c;
    }
}

// expmap0 on packed regs, with analytic out-norm^2 carried
template<int R>
__device__ __forceinline__ void expmap2(ull (&v)[R][4], float (&xn2)[8]) {
    float s2[8];
    ssq2<R>(v, s2);
    float f[8];
#pragma unroll
    for (int t = 0; t < 8; t++) {
        float rn = rnorm_c(s2[t]);
        float n = fmaxf(s2[t], 1e-30f) * rn;
        float tt = tanhf(fminf(kSQC() * n, 15.f));
        float e = tt * rn * kISQC();
        float ny = tt * kISQC();
        float pg = (ny > kMaxN()) ? __fdividef(kMaxN(), ny) : 1.f;
        f[t] = e * pg;
        ny = fminf(ny, kMaxN());
        xn2[t] = ny * ny;
    }
    scale2<R>(v, f);
}

// p_linear core: out = mobius_add(projx(mobius_matvec(W,x)), eb)
// (final projx NOT applied; caller folds it). on2raw = ||out||^2 pre-projx.
template<int K, int SW, int R>
__device__ __forceinline__ void hyplin2(const float* __restrict__ Wc,
                                        const float* __restrict__ eb, float ebn2,
                                        const ull* __restrict__ xb,
                                        const float (&xn2)[8],
                                        ull (&out)[R][4], float (&on2raw)[8]) {
    const int lane = threadIdx.x & 31;
    mvv<K, SW, R>(Wc, xb, out);
    float mn2[8];
    ssq2<R>(out, mn2);
    float tot[8], x2[8];
#pragma unroll
    for (int t = 0; t < 8; t++) {
        float rxn = rnorm_c(xn2[t]);
        float xn = fmaxf(xn2[t], 1e-30f) * rxn;
        float rmn = rnorm_c(mn2[t]);
        float mn = fmaxf(mn2[t], 1e-30f) * rmn;
        float ar = artanh_c(kSQC() * xn);
        float tt = tanhf(fminf(mn * rxn * ar, 15.f));
        float sc = (mn2[t] == 0.f) ? 0.f : tt * rmn * kISQC();
        float nr = (mn2[t] == 0.f) ? 0.f : tt * kISQC();
        float g = (nr > kMaxN()) ? __fdividef(kMaxN(), nr) : 1.f;
        tot[t] = sc * g;
        nr = fminf(nr, kMaxN());
        x2[t] = nr * nr;
    }
    scale2<R>(out, tot);
    float xy[8];
    {
        ull dp[4] = {0ull, 0ull, 0ull, 0ull};
#pragma unroll
        for (int r = 0; r < R; r++) {
            ull ed = pkd(eb[lane + 32 * r]);
#pragma unroll
            for (int p = 0; p < 4; p++) dp[p] = fma2_(out[r][p], ed, dp[p]);
        }
#pragma unroll
        for (int p = 0; p < 4; p++) {
            ull a = wsum2(dp[p]);
            upk2(a, xy[2 * p], xy[2 * p + 1]);
        }
    }
    ull ca[4], cb[4], iv[4];
#pragma unroll
    for (int p = 0; p < 4; p++) {
        float c0[2], c1[2], c2[2];
#pragma unroll
        for (int h = 0; h < 2; h++) {
            int t = 2 * p + h;
            float a = 1.f + 2.f * K_C * xy[t] + K_C * ebn2;
            float b = 1.f - K_C * x2[t];
            float dn = 1.f + 2.f * K_C * xy[t] + K_C * K_C * x2[t] * ebn2;
            c0[h] = a; c1[h] = b;
            c2[h] = __fdividef(1.f, fmaxf(dn, K_MIN));
        }
        ca[p] = pk2(c0[0], c0[1]);
        cb[p] = pk2(c1[0], c1[1]);
        iv[p] = pk2(c2[0], c2[1]);
    }
#pragma unroll
    for (int r = 0; r < R; r++) {
        ull ed = pkd(eb[lane + 32 * r]);
#pragma unroll
        for (int p = 0; p < 4; p++)
            out[r][p] = mul2_(fma2_(ca[p], out[r][p], mul2_(cb[p], ed)), iv[p]);
    }
    ssq2<R>(out, on2raw);
}

// Mob_Act(relu): fold trailing projx + logmap0, relu, expmap0(+projx)
template<int R>
__device__ __forceinline__ void mobrelu2(ull (&v)[R][4], const float (&on2raw)[8],
                                         float (&xn2n)[8]) {
    float f[8];
#pragma unroll
    for (int t = 0; t < 8; t++) {
        float rn = rnorm_c(on2raw[t]);
        float n = fmaxf(on2raw[t], 1e-30f) * rn;
        float pf, nc, rnc;
        if (n > kMaxN()) { pf = __fdividef(kMaxN(), n); nc = kMaxN(); rnc = kIMaxN(); }
        else             { pf = 1.f; nc = n; rnc = rn; }
        float ls = artanh_c(kSQC() * nc) * rnc * kISQC();
        f[t] = pf * ls;
    }
    ull sp[4] = {0ull, 0ull, 0ull, 0ull};
#pragma unroll
    for (int p = 0; p < 4; p++) {
        ull fp = pk2(f[2 * p], f[2 * p + 1]);
#pragma unroll
        for (int r = 0; r < R; r++) {
            ull w = mul2_(v[r][p], fp);
            float a, b;
            upk2(w, a, b);
            a = fmaxf(a, 0.f);
            b = fmaxf(b, 0.f);
            w = pk2(a, b);
            v[r][p] = w;
            sp[p] = fma2_(w, w, sp[p]);
        }
    }
    float s2[8];
#pragma unroll
    for (int p = 0; p < 4; p++) {
        ull a = wsum2(sp[p]);
        upk2(a, s2[2 * p], s2[2 * p + 1]);
    }
#pragma unroll
    for (int t = 0; t < 8; t++) {
        float rn = rnorm_c(s2[t]);
        float n = fmaxf(s2[t], 1e-30f) * rn;
        float tt = tanhf(fminf(kSQC() * n, 15.f));
        float e = tt * rn * kISQC();
        float ny = tt * kISQC();
        float pg = (ny > kMaxN()) ? __fdividef(kMaxN(), ny) : 1.f;
        f[t] = e * pg;
        ny = fminf(ny, kMaxN());
        xn2n[t] = ny * ny;
    }
    scale2<R>(v, f);
}

// ---- cooperative smem loaders ----
// column layout: dst[j*SW + k] = W[j*K + k], zero-padded
__device__ __forceinline__ void loadWtCol(float* dst, const float* __restrict__ W,
                                          int J, int K, int Jrows, int SW) {
    int n = Jrows * SW;
    for (int i = threadIdx.x; i < n; i += blockDim.x) {
        int j = i / SW;
        int k = i - j * SW;
        dst[i] = (j < J && k < K) ? W[j * K + k] : 0.f;
    }
}
__device__ __forceinline__ void loadVec(float* dst, const float* __restrict__ v, int J, int Jpad) {
    for (int i = threadIdx.x; i < Jpad; i += blockDim.x) dst[i] = (i < J) ? v[i] : 0.f;
}

// warp-level expmap0 of a bias vector in smem (padded), also stores ||eb||^2
template<int R>
__device__ __forceinline__ void expmap_smem(float* v, float* n2out) {
    const int lane = threadIdx.x & 31;
    float a[R];
    float p = 0.f;
#pragma unroll
    for (int r = 0; r < R; r++) {
        a[r] = v[lane + 32 * r];
        p = fmaf(a[r], a[r], p);
    }
    p = wsum(p);
    float n = fmaxf(sqrtf(p), K_MIN);
    float tt = tanhf(fminf(kSQC() * n, 15.f));
    float scv = tt / (kSQC() * n);
#pragma unroll
    for (int r = 0; r < R; r++) a[r] *= scv;
    float q = 0.f;
#pragma unroll
    for (int r = 0; r < R; r++) q = fmaf(a[r], a[r], q);
    q = wsum(q);
    float nn = fmaxf(sqrtf(q), K_MIN);
    if (nn > kMaxN()) {
        float fsc = kMaxN() / nn;
#pragma unroll
        for (int r = 0; r < R; r++) a[r] *= fsc;
    }
    float y2 = 0.f;
#pragma unroll
    for (int r = 0; r < R; r++) y2 = fmaf(a[r], a[r], y2);
    y2 = wsum(y2);
#pragma unroll
    for (int r = 0; r < R; r++) v[lane + 32 * r] = a[r];
    if (lane == 0) *n2out = y2;
}

extern __shared__ float sm[];

// SW (row strides, floats): layer1 36, layer2 84, layer3 108, attn 132
// ================= Kernel E: Euclidean branch =================
#define KE_W1 0
#define KE_W2 3456
#define KE_W3 14208
#define KE_B1 28032
#define KE_B2 28128
#define KE_B3 28256
#define KE_XOFF 28384
__global__ void __launch_bounds__(512) kE_kernel(
    const float* __restrict__ x,
    const float* __restrict__ We1, const float* __restrict__ be1,
    const float* __restrict__ We2, const float* __restrict__ be2,
    const float* __restrict__ We3, const float* __restrict__ be3) {
    loadWtCol(sm + KE_W1, We1, 80, 32, 96, 36);
    loadWtCol(sm + KE_W2, We2, 104, 80, 128, 84);
    loadWtCol(sm + KE_W3, We3, 128, 104, 128, 108);
    loadVec(sm + KE_B1, be1, 80, 96);
    loadVec(sm + KE_B2, be2, 104, 128);
    loadVec(sm + KE_B3, be3, 128, 128);
    __syncthreads();

    const int lane = threadIdx.x & 31;
    const int warp = threadIdx.x >> 5;
    const int b = blockIdx.x;
    const int s0 = warp * 8;
    ull* xb = (ull*)(sm + KE_XOFF) + warp * XBW;

    {
        const float* xsrc = x + b * (32 * 128) + lane * 128 + s0;
        float4 a0 = *(const float4*)(xsrc);
        float4 a1 = *(const float4*)(xsrc + 4);
        ull* d = xb + lane * XS;
        ulonglong2 u0; u0.x = pk2(a0.x, a0.y); u0.y = pk2(a0.z, a0.w);
        ulonglong2 u1; u1.x = pk2(a1.x, a1.y); u1.y = pk2(a1.z, a1.w);
        *(ulonglong2*)(d) = u0;
        *(ulonglong2*)(d + 2) = u1;
    }
    __syncwarp();

    ull h1[3][4];
    mvv<32, 36, 3>(sm + KE_W1, xb, h1);
#pragma unroll
    for (int r = 0; r < 3; r++) {
        float bv = sm[KE_B1 + lane + 32 * r];
#pragma unroll
        for (int p = 0; p < 4; p++) {
            float a, c;
            upk2(h1[r][p], a, c);
            h1[r][p] = pk2(fmaxf(a + bv, 0.f), fmaxf(c + bv, 0.f));
        }
    }
    __syncwarp();
    put2<3>(xb, h1);
    __syncwarp();

    ull h2[4][4];
    mvv<80, 84, 4>(sm + KE_W2, xb, h2);
#pragma unroll
    for (int r = 0; r < 4; r++) {
        float bv = sm[KE_B2 + lane + 32 * r];
#pragma unroll
        for (int p = 0; p < 4; p++) {
            float a, c;
            upk2(h2[r][p], a, c);
            h2[r][p] = pk2(fmaxf(a + bv, 0.f), fmaxf(c + bv, 0.f));
        }
    }
    __syncwarp();
    put2<4>(xb, h2);
    __syncwarp();

    ull h3[4][4];
    mvv<104, 108, 4>(sm + KE_W3, xb, h3);
    float* dst = g_oe + (b * SQ + s0) * 128 + lane;
#pragma unroll
    for (int r = 0; r < 4; r++) {
        float bv = sm[KE_B3 + lane + 32 * r];
#pragma unroll
        for (int p = 0; p < 4; p++) {
            float a, c;
            upk2(h3[r][p], a, c);
            dst[(2 * p) * 128 + 32 * r] = fmaxf(a + bv, 0.f);
            dst[(2 * p + 1) * 128 + 32 * r] = fmaxf(c + bv, 0.f);
        }
    }
}

// ================= Kernel H: hyperbolic branch =================
#define KH_E1 28032
#define KH_E2 28128
#define KH_E3 28256
#define KH_N2 28384
#define KH_XOFF 28388
__global__ void __launch_bounds__(512) kH_kernel(
    const float* __restrict__ x,
    const float* __restrict__ Wh1, const float* __restrict__ bh1,
    const float* __restrict__ Wh2, const float* __restrict__ bh2,
    const float* __restrict__ Wh3, const float* __restrict__ bh3) {
    loadWtCol(sm + KE_W1, Wh1, 80, 32, 96, 36);
    loadWtCol(sm + KE_W2, Wh2, 104, 80, 128, 84);
    loadWtCol(sm + KE_W3, Wh3, 128, 104, 128, 108);
    loadVec(sm + KH_E1, bh1, 80, 96);
    loadVec(sm + KH_E2, bh2, 104, 128);
    loadVec(sm + KH_E3, bh3, 128, 128);
    __syncthreads();
    const int warp = threadIdx.x >> 5;
    if (warp == 0) expmap_smem<3>(sm + KH_E1, sm + KH_N2 + 0);
    else if (warp == 1) expmap_smem<4>(sm + KH_E2, sm + KH_N2 + 1);
    else if (warp == 2) expmap_smem<4>(sm + KH_E3, sm + KH_N2 + 2);
    __syncthreads();
    const float e1n2 = sm[KH_N2 + 0], e2n2 = sm[KH_N2 + 1], e3n2 = sm[KH_N2 + 2];

    const int lane = threadIdx.x & 31;
    const int b = blockIdx.x;
    const int s0 = warp * 8;
    ull* xb = (ull*)(sm + KH_XOFF) + warp * XBW;

    ull xh[1][4];
    {
        const float* xsrc = x + b * (32 * 128) + lane * 128 + s0;
        float4 a0 = *(const float4*)(xsrc);
        float4 a1 = *(const float4*)(xsrc + 4);
        xh[0][0] = pk2(a0.x, a0.y);
        xh[0][1] = pk2(a0.z, a0.w);
        xh[0][2] = pk2(a1.x, a1.y);
        xh[0][3] = pk2(a1.z, a1.w);
    }
    float xn2[8];
    expmap2<1>(xh, xn2);
    __syncwarp();
    put2<1>(xb, xh);
    __syncwarp();

    ull y1[3][4];
    float on2[8];
    hyplin2<32, 36, 3>(sm + KE_W1, sm + KH_E1, e1n2, xb, xn2, y1, on2);
    mobrelu2<3>(y1, on2, xn2);
    __syncwarp();
    put2<3>(xb, y1);
    __syncwarp();

    ull y2[4][4];
    hyplin2<80, 84, 4>(sm + KE_W2, sm + KH_E2, e2n2, xb, xn2, y2, on2);
    mobrelu2<4>(y2, on2, xn2);
    __syncwarp();
    put2<4>(xb, y2);
    __syncwarp();

    ull y3[4][4];
    hyplin2<104, 108, 4>(sm + KE_W3, sm + KH_E3, e3n2, xb, xn2, y3, on2);
    float pf[8], nn[8];
#pragma unroll
    for (int t = 0; t < 8; t++) {
        float rn = rnorm_c(on2[t]);
        float n = fmaxf(on2[t], 1e-30f) * rn;
        pf[t] = (n > kMaxN()) ? __fdividef(kMaxN(), n) : 1.f;
        float nc = fminf(n, kMaxN());
        nn[t] = nc * nc;
    }
    float* dst = g_oh + (b * SQ + s0) * 128 + lane;
#pragma unroll
    for (int r = 0; r < 4; r++)
#pragma unroll
        for (int p = 0; p < 4; p++) {
            float a, c;
            upk2(y3[r][p], a, c);
            dst[(2 * p) * 128 + 32 * r] = a * pf[2 * p];
            dst[(2 * p + 1) * 128 + 32 * r] = c * pf[2 * p + 1];
        }
#pragma unroll
    for (int t = 0; t < 8; t++)
        if (lane == t) g_ohn2[b * SQ + s0 + t] = nn[t];
}

// ========== Kernel 2: attention + pooling + classifier ==========
// one weight slab (16896 floats @ SW=132) reused for Wae then Wah
#define K2_W   0
#define K2_BAE 16896
#define K2_EBH 17024
#define K2_WTE 17152
#define K2_WTH 17280
#define K2_SCA 17408
#define K2_OS  17412
#define K2_HS  17668
#define K2_XOFF 17684
__global__ void __launch_bounds__(512) k2_kernel(
    const float* __restrict__ Wae, const float* __restrict__ bae,
    const float* __restrict__ Wah, const float* __restrict__ bah,
    const float* __restrict__ Wte, const float* __restrict__ bte,
    const float* __restrict__ Wth, const float* __restrict__ bth,
    const float* __restrict__ Wf1, const float* __restrict__ bf1,
    const float* __restrict__ Wf2, const float* __restrict__ bf2,
    float* __restrict__ out) {
    loadWtCol(sm + K2_W, Wae, 128, 128, 128, 132);
    loadVec(sm + K2_BAE, bae, 128, 128);
    loadVec(sm + K2_EBH, bah, 128, 128);
    loadVec(sm + K2_WTE, Wte, 128, 128);
    loadVec(sm + K2_WTH, Wth, 128, 128);
    __syncthreads();
    const int warp = threadIdx.x >> 5;
    const int lane = threadIdx.x & 31;
    if (warp == 0) expmap_smem<4>(sm + K2_EBH, sm + K2_SCA);
    __syncthreads();
    const float ebn2 = sm[K2_SCA];
    const float bte0 = bte[0], bth0 = bth[0];
    const int b = blockIdx.x, s0 = warp * 8;
    ull* xb = (ull*)(sm + K2_XOFF) + warp * XBW;

    // ---- stage oe, compute tan_e ----
    {
        const float* src = g_oe + (b * SQ + s0) * 128;
#pragma unroll
        for (int r = 0; r < 4; r++) {
            int k = lane + 32 * r;
            float v[8];
#pragma unroll
            for (int t = 0; t < 8; t++) v[t] = src[t * 128 + k];
            ull* d = xb + k * XS;
            ulonglong2 u0; u0.x = pk2(v[0], v[1]); u0.y = pk2(v[2], v[3]);
            ulonglong2 u1; u1.x = pk2(v[4], v[5]); u1.y = pk2(v[6], v[7]);
            *(ulonglong2*)(d) = u0;
            *(ulonglong2*)(d + 2) = u1;
        }
    }
    __syncwarp();
    ull te[4][4];
    mvv<128, 132, 4>(sm + K2_W, xb, te);
#pragma unroll
    for (int r = 0; r < 4; r++) {
        ull bv = pkd(sm[K2_BAE + lane + 32 * r]);
#pragma unroll
        for (int p = 0; p < 4; p++) te[r][p] = add2_(te[r][p], bv);
    }

    // ---- swap weight slab to Wah ----
    __syncthreads();
    loadWtCol(sm + K2_W, Wah, 128, 128, 128, 132);
    __syncthreads();

    // ---- stage oh, compute tan_h ----
    {
        const float* src = g_oh + (b * SQ + s0) * 128;
#pragma unroll
        for (int r = 0; r < 4; r++) {
            int k = lane + 32 * r;
            float v[8];
#pragma unroll
            for (int t = 0; t < 8; t++) v[t] = src[t * 128 + k];
            ull* d = xb + k * XS;
            ulonglong2 u0; u0.x = pk2(v[0], v[1]); u0.y = pk2(v[2], v[3]);
            ulonglong2 u1; u1.x = pk2(v[4], v[5]); u1.y = pk2(v[6], v[7]);
            *(ulonglong2*)(d) = u0;
            *(ulonglong2*)(d + 2) = u1;
        }
    }
    float xn2[8];
#pragma unroll
    for (int t = 0; t < 8; t++) xn2[t] = g_ohn2[b * SQ + s0 + t];
    __syncwarp();

    ull th[4][4];
    float on2[8];
    hyplin2<128, 132, 4>(sm + K2_W, sm + K2_EBH, ebn2, xb, xn2, th, on2);
    {
        float f[8];
#pragma unroll
        for (int t = 0; t < 8; t++) {
            float rn = rnorm_c(on2[t]);
            float n = fmaxf(on2[t], 1e-30f) * rn;
            float pf, nc, rnc;
            if (n > kMaxN()) { pf = __fdividef(kMaxN(), n); nc = kMaxN(); rnc = kIMaxN(); }
            else             { pf = 1.f; nc = n; rnc = rn; }
            float ls = artanh_c(kSQC() * nc) * rnc * kISQC();
            f[t] = pf * ls;
        }
        scale2<4>(th, f);
    }

    // ---- attention scores ----
    float ae[8], ah[8];
    {
        ull pa[4] = {0ull, 0ull, 0ull, 0ull};
        ull pb[4] = {0ull, 0ull, 0ull, 0ull};
        const ull hp = pkd(0.5f), hn = pkd(-0.5f);
#pragma unroll
        for (int r = 0; r < 4; r++) {
            ull wa = pkd(sm[K2_WTE + lane + 32 * r]);
            ull wb = pkd(sm[K2_WTH + lane + 32 * r]);
#pragma unroll
            for (int p = 0; p < 4; p++) {
                ull d = fma2_(te[r][p], hp, mul2_(th[r][p], hn));
                pa[p] = fma2_(wa, d, pa[p]);
                pb[p] = fma2_(wb, d, pb[p]);
            }
        }
#pragma unroll
        for (int p = 0; p < 4; p++) {
            ull a = wsum2(pa[p]);
            ull c = wsum2(pb[p]);
            float a0, a1, c0, c1;
            upk2(a, a0, a1);
            upk2(c, c0, c1);
            ae[2 * p] = a0 + bte0;
            ae[2 * p + 1] = a1 + bte0;
            ah[2 * p] = bth0 - c0;
            ah[2 * p + 1] = bth0 - c1;
        }
    }
    float w0[8], w1[8];
#pragma unroll
    for (int t = 0; t < 8; t++) {
        float m = fmaxf(ae[t], ah[t]);
        float e0 = __expf(ae[t] - m), e1 = __expf(ah[t] - m);
        float inv = __fdividef(1.f, e0 + e1);
        w0[t] = e0 * inv;
        w1[t] = e1 * inv;
    }

    // ---- proc_e = w0 * out_e (reload oe from gmem), pool ----
    float acce[4];
    {
        const float* pe = g_oe + (b * SQ + s0) * 128 + lane;
#pragma unroll
        for (int r = 0; r < 4; r++) {
            float s = 0.f;
#pragma unroll
            for (int t = 0; t < 8; t++) s = fmaf(w0[t], pe[t * 128 + 32 * r], s);
            acce[r] = s;
        }
    }

    // ---- proc_h = logmap0(projx(mobius_scalar_mul(w1, out_h))), pool ----
    // oh still staged in xb
    float acch[4];
    {
        float tt[8];
#pragma unroll
        for (int t = 0; t < 8; t++) {
            float rn = rnorm_c(xn2[t]);
            float n = fmaxf(xn2[t], 1e-30f) * rn;
            float ar = artanh_c(kSQC() * n);
            float q = tanhf(fminf(w1[t] * ar, 15.f));
            float sc = q * rn * kISQC();
            float qn = q * kISQC();
            float pg = (qn > kMaxN()) ? __fdividef(kMaxN(), qn) : 1.f;
            float qc = fmaxf(fminf(qn, kMaxN()), K_MIN);
            float ls = artanh_c(kSQC() * qc) * __fdividef(1.f, kSQC() * qc);
            tt[t] = sc * pg * ls;
        }
        ull tp[4];
#pragma unroll
        for (int p = 0; p < 4; p++) tp[p] = pk2(tt[2 * p], tt[2 * p + 1]);
#pragma unroll
        for (int r = 0; r < 4; r++) {
            const ull* d = xb + (lane + 32 * r) * XS;
            ulonglong2 u0 = *(const ulonglong2*)(d);
            ulonglong2 u1 = *(const ulonglong2*)(d + 2);
            ull a = mul2_(tp[0], u0.x);
            a = fma2_(tp[1], u0.y, a);
            a = fma2_(tp[2], u1.x, a);
            a = fma2_(tp[3], u1.y, a);
            float x0, x1;
            upk2(a, x0, x1);
            acch[r] = x0 + x1;
        }
    }

    // partials into the (now-dead) xbuf region
    float* pes = sm + K2_XOFF;          // 2048 floats
    float* phs = pes + 2048;            // 2048 floats
    __syncthreads();
#pragma unroll
    for (int r = 0; r < 4; r++) {
        pes[warp * 128 + lane + 32 * r] = acce[r];
        phs[warp * 128 + lane + 32 * r] = acch[r];
    }
    __syncthreads();

    float* os = sm + K2_OS;
    float* hs = sm + K2_HS;
    for (int j = threadIdx.x; j < 256; j += 512) {
        const float* src = (j < 128) ? (pes + j) : (phs + (j - 128));
        float s = 0.f;
#pragma unroll
        for (int i = 0; i < 16; i++) s += src[i * 128];
        os[j] = s * (1.0f / 128.0f);
    }
    __syncthreads();

    if (threadIdx.x < 32) {
        if (lane < 10) {
            float h = bf1[lane];
            for (int i = 0; i < 256; i++) h = fmaf(Wf1[lane * 256 + i], os[i], h);
            hs[lane] = fmaxf(h, 0.f);
        }
        __syncwarp();
        if (lane < 10) {
            float o2 = bf2[lane];
#pragma unroll
            for (int i = 0; i < 10; i++) o2 = fmaf(Wf2[lane * 10 + i], hs[i], o2);
            out[b * 10 + lane] = o2;
        }
    }
}

extern "C" void kernel_launch(void* const* d_in, const int* in_sizes, int n_in,
                              void* d_out, int out_size) {
    (void)in_sizes; (void)n_in; (void)out_size;
    const float* x   = (const float*)d_in[0];
    const float* We1 = (const float*)d_in[1];  const float* be1 = (const float*)d_in[2];
    const float* We2 = (const float*)d_in[3];  const float* be2 = (const float*)d_in[4];
    const float* We3 = (const float*)d_in[5];  const float* be3 = (const float*)d_in[6];
    const float* Wh1 = (const float*)d_in[7];  const float* bh1 = (const float*)d_in[8];
    const float* Wh2 = (const float*)d_in[9];  const float* bh2 = (const float*)d_in[10];
    const float* Wh3 = (const float*)d_in[11]; const float* bh3 = (const float*)d_in[12];
    const float* Wae = (const float*)d_in[13]; const float* bae = (const float*)d_in[14];
    const float* Wah = (const float*)d_in[15]; const float* bah = (const float*)d_in[16];
    const float* Wte = (const float*)d_in[17]; const float* bte = (const float*)d_in[18];
    const float* Wth = (const float*)d_in[19]; const float* bth = (const float*)d_in[20];
    const float* Wf1 = (const float*)d_in[21]; const float* bf1 = (const float*)d_in[22];
    const float* Wf2 = (const float*)d_in[23]; const float* bf2 = (const float*)d_in[24];
    float* out = (float*)d_out;

    size_t smE = (size_t)(KE_XOFF + 16 * XBW * 2) * sizeof(float);
    size_t smH = (size_t)(KH_XOFF + 16 * XBW * 2) * sizeof(float);
    size_t sm2 = (size_t)(K2_XOFF + 16 * XBW * 2) * sizeof(float);

    cudaFuncSetAttribute(kE_kernel, cudaFuncAttributeMaxDynamicSharedMemorySize, (int)smE);
    cudaFuncSetAttribute(kH_kernel, cudaFuncAttributeMaxDynamicSharedMemorySize, (int)smH);
    cudaFuncSetAttribute(k2_kernel, cudaFuncAttributeMaxDynamicSharedMemorySize, (int)sm2);

    kE_kernel<<<NB, 512, smE>>>(x, We1, be1, We2, be2, We3, be3);
    kH_kernel<<<NB, 512, smH>>>(x, Wh1, bh1, Wh2, bh2, Wh3, bh3);
    k2_kernel<<<NB, 512, sm2>>>(Wae, bae, Wah, bah, Wte, bte, Wth, bth,
                                Wf1, bf1, Wf2, bf2, out);
}